// round 11
// baseline (speedup 1.0000x reference)
#include <cuda_runtime.h>
#include <math.h>

// Problem constants
#define B  32
#define C  200
#define H  56
#define W  56
#define HW 3136
#define OH 224
#define OW 224
#define KS 33

#define MSP2 68         // 64x64 chunk pitch (floats); 272B rows, 16B aligned

// Scratch (device globals) — g_delta layout: [hw][c][b]
__device__ float g_delta[(size_t)HW * C * B];
__device__ float g_dist[(size_t)B * HW];          // [b][hw]
__device__ float g_tmp[(size_t)B * 56 * OW];      // [b][y56][x224]
__device__ float g_K[OH * 56];                    // combined blur*upsample [y][s]
__device__ float g_KT[56 * OH];                   // transposed [s][y]

// ---------------- packed f32x2 helpers ----------------
__device__ __forceinline__ unsigned long long fma2(unsigned long long a,
                                                   unsigned long long b,
                                                   unsigned long long c)
{
    unsigned long long d;
    asm("fma.rn.f32x2 %0, %1, %2, %3;" : "=l"(d) : "l"(a), "l"(b), "l"(c));
    return d;
}
__device__ __forceinline__ unsigned long long pack2(float x)
{
    unsigned long long d;
    asm("mov.b64 %0, {%1, %1};" : "=l"(d) : "f"(x));
    return d;
}
__device__ __forceinline__ float2 unpack2(unsigned long long v)
{
    float2 r;
    asm("mov.b64 {%0, %1}, %2;" : "=f"(r.x), "=f"(r.y) : "l"(v));
    return r;
}

// ---------------------------------------------------------------------------
// Kernel 1: delta transpose prepass: emb[b][c][hw] -> g_delta[hw][c][b]
// ---------------------------------------------------------------------------
__global__ void prep_delta_kernel(const float* __restrict__ emb,
                                  const float* __restrict__ mean)
{
    __shared__ float s[8][32][33];
    const int hw0 = blockIdx.x * 32;
    const int c0  = blockIdx.y * 8;
    const int lane = threadIdx.x & 31;
    const int wrp  = threadIdx.x >> 5;

    const int c = c0 + wrp;
    const float m = mean[(size_t)c * HW + hw0 + lane];
    #pragma unroll 4
    for (int b = 0; b < B; b++) {
        float e = emb[((size_t)b * C + c) * HW + hw0 + lane];
        s[wrp][b][lane] = e - m;
    }
    __syncthreads();

    const int b  = threadIdx.x & 31;
    const int cl = threadIdx.x >> 5;
    #pragma unroll 4
    for (int hwl = 0; hwl < 32; hwl++) {
        g_delta[(size_t)(hw0 + hwl) * (C * B) + (c0 + cl) * B + b] = s[cl][b][hwl];
    }
}

// ---------------------------------------------------------------------------
// Kernel 2: per-pixel mahalanobis, symmetric 64x64 schedule.
// Geometry: 256 thr = 2 jg x 16 ty x 8 tx. Each thread: 4 rows (ty+16r) x
// 4 batches over a 32-column j-subrange (jg). Same total work as R8 but
// 2x warps for latency hiding (6 warps/SMSP at 3 CTAs/SM).
// ---------------------------------------------------------------------------
__global__ void __launch_bounds__(256)
mahal_kernel(const float* __restrict__ invcov)
{
    extern __shared__ float sm[];
    float* Ds  = sm;                      // 6400 floats [j][b]
    float* Mb0 = sm + C * B;              // 64*68
    float* Mb1 = Mb0 + 64 * MSP2;         // 64*68 (also border staging)

    const int p   = blockIdx.x;
    const int tid = threadIdx.x;
    const int tx  = tid & 7;
    const int g   = tid >> 3;             // 0..31 (group = jg*16 + ty)
    const int ty  = g & 15;               // 0..15
    const int jg  = g >> 4;               // 0..1
    const int b0  = tx * 4;

    const float* Mp = invcov + (size_t)p * (C * C);

    // chunk schedule: (I,J,weight); 64-blocks, J <= I
    const int   CI[6] = {0, 1, 1, 2, 2, 2};
    const int   CJ[6] = {0, 0, 1, 0, 1, 2};
    const float CW[6] = {1.f, 2.f, 1.f, 2.f, 2.f, 1.f};

    // ---- issue chunk 0 LDGs first (1024 float4 / 256 thr = 4 each) ----
    float4 st[4];
    #pragma unroll
    for (int o = 0; o < 4; o++) {
        int e4 = o * 256 + tid;
        int il = e4 >> 4;
        int jl = (e4 & 15) * 4;
        st[o] = *(const float4*)&Mp[(size_t)il * C + jl];
    }

    // ---- stage delta (coalesced) ----
    const float* dsrc = g_delta + (size_t)p * (C * B);
    for (int i = tid * 4; i < C * B; i += 1024)
        *(float4*)&Ds[i] = *(const float4*)&dsrc[i];

    // ---- stage border rows 192..199 (8 x 200) into Mb1 ----
    for (int i = tid * 4; i < 8 * C; i += 1024)
        *(float4*)&Mb1[i] = *(const float4*)&Mp[(size_t)192 * C + i];

    __syncthreads();

    float q0 = 0.f, q1 = 0.f, q2 = 0.f, q3 = 0.f;

    // ---- border strip: rows 192..199, col-weight 2 (j<192) / 1 ----
    #pragma unroll
    for (int rr = 0; rr < 8; rr++) {
        const float* mrow = &Mb1[rr * C];
        float p0 = 0.f, p1 = 0.f, p2 = 0.f, p3 = 0.f;
        #pragma unroll
        for (int s = 0; s < 6; s++) {             // j = g + 32s < 192
            int j = g + 32 * s;
            float wm = 2.f * mrow[j];
            float4 dj = *(const float4*)&Ds[j * B + b0];
            p0 += wm * dj.x; p1 += wm * dj.y;
            p2 += wm * dj.z; p3 += wm * dj.w;
        }
        if (g < 8) {                               // j = 192 + g, weight 1
            int j = 192 + g;
            float wm = mrow[j];
            float4 dj = *(const float4*)&Ds[j * B + b0];
            p0 += wm * dj.x; p1 += wm * dj.y;
            p2 += wm * dj.z; p3 += wm * dj.w;
        }
        float4 di = *(const float4*)&Ds[(192 + rr) * B + b0];
        q0 += di.x * p0; q1 += di.y * p1; q2 += di.z * p2; q3 += di.w * p3;
    }

    // ---- 6-chunk pipeline over 64x64 blocks, register-staged double buffer ----
    #pragma unroll
    for (int k = 0; k < 6; k++) {
        float* buf = (k & 1) ? Mb1 : Mb0;
        __syncthreads();                       // prior readers of buf done
        #pragma unroll
        for (int o = 0; o < 4; o++) {
            int e4 = o * 256 + tid;
            int il = e4 >> 4;
            int jl = (e4 & 15) * 4;
            *(float4*)&buf[il * MSP2 + jl] = st[o];
        }
        __syncthreads();

        if (k < 5) {                           // prefetch next chunk
            const float* src = Mp + (size_t)(64 * CI[k + 1]) * C + 64 * CJ[k + 1];
            #pragma unroll
            for (int o = 0; o < 4; o++) {
                int e4 = o * 256 + tid;
                int il = e4 >> 4;
                int jl = (e4 & 15) * 4;
                st[o] = *(const float4*)&src[(size_t)il * C + jl];
            }
        }

        // ---- compute chunk k: 4 rows x 4 batches over 32-col subrange ----
        unsigned long long acc[4][2];
        #pragma unroll
        for (int r = 0; r < 4; r++) { acc[r][0] = 0ull; acc[r][1] = 0ull; }

        const float* dbase = &Ds[(64 * CJ[k] + jg * 32) * B + b0];
        const int mcol = jg * 32;
        #pragma unroll
        for (int u = 0; u < 8; u++) {
            float4 mv[4];
            #pragma unroll
            for (int r = 0; r < 4; r++)
                mv[r] = *(const float4*)&buf[(ty + 16 * r) * MSP2 + mcol + u * 4];
            #pragma unroll
            for (int jj = 0; jj < 4; jj++) {
                ulonglong2 du = *(const ulonglong2*)(dbase + (u * 4 + jj) * B);
                #pragma unroll
                for (int r = 0; r < 4; r++) {
                    float c = (jj == 0) ? mv[r].x : (jj == 1) ? mv[r].y
                            : (jj == 2) ? mv[r].z : mv[r].w;
                    unsigned long long m = pack2(c);
                    acc[r][0] = fma2(m, du.x, acc[r][0]);
                    acc[r][1] = fma2(m, du.y, acc[r][1]);
                }
            }
        }

        // ---- fold with weight (partial over this jg's columns) ----
        {
            const float w = CW[k];
            #pragma unroll
            for (int r = 0; r < 4; r++) {
                int i = 64 * CI[k] + ty + 16 * r;
                float4 dv = *(const float4*)&Ds[i * B + b0];
                float2 s0 = unpack2(acc[r][0]);
                float2 s1 = unpack2(acc[r][1]);
                q0 += w * dv.x * s0.x;
                q1 += w * dv.y * s0.y;
                q2 += w * dv.z * s1.x;
                q3 += w * dv.w * s1.y;
            }
        }
    }

    // ---- block reduction over 32 groups per b ----
    __syncthreads();
    float* red = Mb0;                   // 32*33 floats scratch
    red[g * 33 + b0 + 0] = q0;
    red[g * 33 + b0 + 1] = q1;
    red[g * 33 + b0 + 2] = q2;
    red[g * 33 + b0 + 3] = q3;
    __syncthreads();
    if (tid < B) {
        float acc = 0.f;
        #pragma unroll
        for (int t = 0; t < 32; t++) acc += red[t * 33 + tid];
        g_dist[(size_t)tid * HW + p] = sqrtf(fmaxf(acc, 0.f));
    }
}

// ---------------------------------------------------------------------------
// Kernel 3: build combined operator K = G(blur, reflect-pad) * U(bilinear
// upsample, half-pixel, edge-clamp). K[y][s], y in [0,224), s in [0,56).
// ---------------------------------------------------------------------------
__global__ void kinit_kernel()
{
    __shared__ float g[KS];
    const int y = threadIdx.x;
    if (y < KS) {
        float x = (float)(y - 16);
        g[y] = expf(-(x * x) / 32.f);
    }
    __syncthreads();
    float gs = 0.f;
    #pragma unroll
    for (int i = 0; i < KS; i++) gs += g[i];
    const float inv = 1.f / gs;

    float acc[56];
    #pragma unroll
    for (int s = 0; s < 56; s++) acc[s] = 0.f;

    for (int k = 0; k < KS; k++) {
        int t = y + k - 16;
        if (t < 0) t = -t;
        if (t > OH - 1) t = 2 * (OH - 1) - t;
        float src = 0.25f * t - 0.375f;
        float fs = floorf(src);
        int s0 = (int)fs;
        float a = src - fs;
        int sa = min(max(s0, 0), 55);
        int sb = min(max(s0 + 1, 0), 55);
        float w = g[k] * inv;
        acc[sa] += w * (1.f - a);
        acc[sb] += w * a;
    }
    for (int s = 0; s < 56; s++) {
        g_K[y * 56 + s] = acc[s];
        g_KT[s * OH + y] = acc[s];
    }
}

// ---------------------------------------------------------------------------
// Kernel 4: pass1 (horizontal): tmp[b][y56][x] = sum_s K[x][s] * dist[b][y][s]
// grid = B*14 (4 y-rows per block), block 224.
// ---------------------------------------------------------------------------
__global__ void __launch_bounds__(224)
pass1_kernel()
{
    __shared__ float drow[4][56];
    const int b   = blockIdx.x / 14;
    const int yc0 = (blockIdx.x % 14) * 4;
    const int x   = threadIdx.x;

    for (int i = threadIdx.x; i < 4 * 56; i += 224)
        drow[i / 56][i % 56] = g_dist[(size_t)b * HW + (yc0 + i / 56) * 56 + (i % 56)];
    __syncthreads();

    float acc[4];
    #pragma unroll
    for (int r = 0; r < 4; r++) acc[r] = 0.f;

    #pragma unroll 8
    for (int s = 0; s < 56; s++) {
        float w = g_KT[s * OH + x];
        #pragma unroll
        for (int r = 0; r < 4; r++) acc[r] += w * drow[r][s];
    }
    #pragma unroll
    for (int r = 0; r < 4; r++)
        g_tmp[((size_t)b * 56 + yc0 + r) * OW + x] = acc[r];
}

// ---------------------------------------------------------------------------
// Kernel 5: pass2 (vertical): out[b][y][x] = sum_s K[y][s] * tmp[b][s][x]
// grid = B*8 (28 y-rows per block), block 224. tmp slab (56x224) in smem.
// ---------------------------------------------------------------------------
__global__ void __launch_bounds__(224)
pass2_kernel(float* __restrict__ out)
{
    extern __shared__ float p2[];
    float* slab = p2;              // 56*224 = 12544 floats
    float* Ks   = p2 + 56 * OW;    // 28*56  = 1568 floats

    const int b  = blockIdx.x >> 3;
    const int y0 = (blockIdx.x & 7) * 28;
    const int x  = threadIdx.x;

    const float* tsrc = g_tmp + (size_t)b * 56 * OW;
    for (int i = threadIdx.x; i < 56 * OW; i += 224) slab[i] = tsrc[i];
    for (int i = threadIdx.x; i < 28 * 56; i += 224)
        Ks[i] = g_K[(y0 + i / 56) * 56 + (i % 56)];
    __syncthreads();

    #pragma unroll 4
    for (int yy = 0; yy < 28; yy++) {
        float acc = 0.f;
        #pragma unroll 8
        for (int s = 0; s < 56; s++)
            acc += Ks[yy * 56 + s] * slab[s * OW + x];
        out[((size_t)b * OH + y0 + yy) * OW + x] = acc;
    }
}

// ---------------------------------------------------------------------------
// Launch
// ---------------------------------------------------------------------------
extern "C" void kernel_launch(void* const* d_in, const int* in_sizes, int n_in,
                              void* d_out, int out_size)
{
    const float* emb    = (const float*)d_in[0];
    const float* mean   = (const float*)d_in[1];
    const float* invcov = (const float*)d_in[2];
    float* out = (float*)d_out;

    const int mahal_smem = (C * B + 2 * 64 * MSP2) * (int)sizeof(float);  // 60416
    cudaFuncSetAttribute(mahal_kernel,
                         cudaFuncAttributeMaxDynamicSharedMemorySize, mahal_smem);
    const int p2_smem = (56 * OW + 28 * 56) * (int)sizeof(float);         // 56448
    cudaFuncSetAttribute(pass2_kernel,
                         cudaFuncAttributeMaxDynamicSharedMemorySize, p2_smem);

    kinit_kernel<<<1, 224>>>();

    dim3 prep_grid(HW / 32, C / 8);
    prep_delta_kernel<<<prep_grid, 256>>>(emb, mean);

    mahal_kernel<<<HW, 256, mahal_smem>>>(invcov);

    pass1_kernel<<<B * 14, 224>>>();
    pass2_kernel<<<B * 8, 224, p2_smem>>>(out);
}

// round 12
// speedup vs baseline: 1.0384x; 1.0384x over previous
#include <cuda_runtime.h>
#include <math.h>

// Problem constants
#define B  32
#define C  200
#define H  56
#define W  56
#define HW 3136
#define OH 224
#define OW 224
#define KS 33

#define MBP 36          // 64x32 M-chunk pitch (floats); 144B rows

// Scratch (device globals) — g_delta layout: [hw][c][b]
__device__ float g_delta[(size_t)HW * C * B];
__device__ float g_dist[(size_t)B * HW];          // [b][hw]
__device__ float g_tmp[(size_t)B * 56 * OW];      // [b][y56][x224]
__device__ float g_K[OH * 56];                    // combined blur*upsample [y][s]
__device__ float g_KT[56 * OH];                   // transposed [s][y]

// ---------------- packed f32x2 helpers ----------------
__device__ __forceinline__ unsigned long long fma2(unsigned long long a,
                                                   unsigned long long b,
                                                   unsigned long long c)
{
    unsigned long long d;
    asm("fma.rn.f32x2 %0, %1, %2, %3;" : "=l"(d) : "l"(a), "l"(b), "l"(c));
    return d;
}
__device__ __forceinline__ unsigned long long pack2(float x)
{
    unsigned long long d;
    asm("mov.b64 %0, {%1, %1};" : "=l"(d) : "f"(x));
    return d;
}
__device__ __forceinline__ float2 unpack2(unsigned long long v)
{
    float2 r;
    asm("mov.b64 {%0, %1}, %2;" : "=f"(r.x), "=f"(r.y) : "l"(v));
    return r;
}

// ---------------------------------------------------------------------------
// Kernel 1: delta transpose prepass: emb[b][c][hw] -> g_delta[hw][c][b]
// ---------------------------------------------------------------------------
__global__ void prep_delta_kernel(const float* __restrict__ emb,
                                  const float* __restrict__ mean)
{
    __shared__ float s[8][32][33];
    const int hw0 = blockIdx.x * 32;
    const int c0  = blockIdx.y * 8;
    const int lane = threadIdx.x & 31;
    const int wrp  = threadIdx.x >> 5;

    const int c = c0 + wrp;
    const float m = mean[(size_t)c * HW + hw0 + lane];
    #pragma unroll 4
    for (int b = 0; b < B; b++) {
        float e = emb[((size_t)b * C + c) * HW + hw0 + lane];
        s[wrp][b][lane] = e - m;
    }
    __syncthreads();

    const int b  = threadIdx.x & 31;
    const int cl = threadIdx.x >> 5;
    #pragma unroll 4
    for (int hwl = 0; hwl < 32; hwl++) {
        g_delta[(size_t)(hw0 + hwl) * (C * B) + (c0 + cl) * B + b] = s[cl][b][hwl];
    }
}

// ---------------------------------------------------------------------------
// Kernel 2: per-pixel mahalanobis, symmetric schedule over 64x32 chunks
// (12 chunks = 6 symmetric 64x64 blocks split in J).
// Geometry: R8-proven 128 thr = 2 jg x 8 ty x 8 tx; 8 rows x 4 batches per
// thread over a 16-col subrange. Single M buffer, register-staged prefetch.
// smem = 25.6KB (Ds) + 9.2KB (Mb) -> 5 CTAs/SM.
// ---------------------------------------------------------------------------
__global__ void __launch_bounds__(128, 5)
mahal_kernel(const float* __restrict__ invcov)
{
    extern __shared__ float sm[];
    float* Ds = sm;                       // 6400 floats [j][b]
    float* Mb = sm + C * B;               // 64*36 floats (also border staging)

    const int p   = blockIdx.x;
    const int tid = threadIdx.x;
    const int tx  = tid & 7;
    const int g   = tid >> 3;             // 0..15 (group = jg*8 + ty)
    const int ty  = g & 7;                // 0..7
    const int jg  = g >> 3;               // 0..1
    const int b0  = tx * 4;

    const float* Mp = invcov + (size_t)p * (C * C);

    // 12-chunk schedule: 64-row block I, 32-col unit Jc, weight
    // derived from symmetric (I,J,w): {0,0,1},{1,0,2},{1,1,1},{2,0,2},{2,1,2},{2,2,1}
    const int   CI2[12] = {0,0, 1,1, 1,1, 2,2, 2,2, 2,2};
    const int   CJc[12] = {0,1, 0,1, 2,3, 0,1, 2,3, 4,5};
    const float CW2[12] = {1.f,1.f, 2.f,2.f, 1.f,1.f, 2.f,2.f, 2.f,2.f, 1.f,1.f};

    // ---- issue chunk 0 LDGs first (512 float4 / 128 thr = 4 each) ----
    float4 st[4];
    #pragma unroll
    for (int o = 0; o < 4; o++) {
        int e4 = o * 128 + tid;           // 512 float4 = 64 rows x 8
        int il = e4 >> 3;
        int jl = (e4 & 7) * 4;
        st[o] = *(const float4*)&Mp[(size_t)il * C + jl];
    }

    // ---- stage delta (coalesced) ----
    const float* dsrc = g_delta + (size_t)p * (C * B);
    #pragma unroll
    for (int i = tid * 4; i < C * B; i += 512)
        *(float4*)&Ds[i] = *(const float4*)&dsrc[i];

    // ---- stage border rows 192..199 (8 x 200 = 1600 floats) into Mb ----
    #pragma unroll
    for (int i = tid * 4; i < 8 * C; i += 512)
        *(float4*)&Mb[i] = *(const float4*)&Mp[(size_t)192 * C + i];

    __syncthreads();

    float q0 = 0.f, q1 = 0.f, q2 = 0.f, q3 = 0.f;

    // ---- border strip: rows 192..199, col-weight 2 (j<192) / 1 ----
    #pragma unroll
    for (int rr = 0; rr < 8; rr++) {
        const float* mrow = &Mb[rr * C];
        float p0 = 0.f, p1 = 0.f, p2 = 0.f, p3 = 0.f;
        #pragma unroll
        for (int s = 0; s < 12; s++) {            // j = g + 16s < 192
            int j = g + 16 * s;
            float wm = 2.f * mrow[j];
            float4 dj = *(const float4*)&Ds[j * B + b0];
            p0 += wm * dj.x; p1 += wm * dj.y;
            p2 += wm * dj.z; p3 += wm * dj.w;
        }
        if (g < 8) {                               // j = 192 + g, weight 1
            int j = 192 + g;
            float wm = mrow[j];
            float4 dj = *(const float4*)&Ds[j * B + b0];
            p0 += wm * dj.x; p1 += wm * dj.y;
            p2 += wm * dj.z; p3 += wm * dj.w;
        }
        float4 di = *(const float4*)&Ds[(192 + rr) * B + b0];
        q0 += di.x * p0; q1 += di.y * p1; q2 += di.z * p2; q3 += di.w * p3;
    }

    // ---- 12-chunk pipeline over 64x32 blocks, single smem buffer ----
    #pragma unroll
    for (int k = 0; k < 12; k++) {
        __syncthreads();                       // prior readers of Mb done
        #pragma unroll
        for (int o = 0; o < 4; o++) {
            int e4 = o * 128 + tid;
            int il = e4 >> 3;
            int jl = (e4 & 7) * 4;
            *(float4*)&Mb[il * MBP + jl] = st[o];
        }
        __syncthreads();

        if (k < 11) {                          // prefetch next chunk
            const float* src = Mp + (size_t)(64 * CI2[k + 1]) * C + 32 * CJc[k + 1];
            #pragma unroll
            for (int o = 0; o < 4; o++) {
                int e4 = o * 128 + tid;
                int il = e4 >> 3;
                int jl = (e4 & 7) * 4;
                st[o] = *(const float4*)&src[(size_t)il * C + jl];
            }
        }

        // ---- compute chunk k: 8 rows x 4 batches over 16-col subrange ----
        unsigned long long acc[8][2];
        #pragma unroll
        for (int r = 0; r < 8; r++) { acc[r][0] = 0ull; acc[r][1] = 0ull; }

        const float* dbase = &Ds[(32 * CJc[k] + jg * 16) * B + b0];
        const int mcol = jg * 16;
        #pragma unroll
        for (int u = 0; u < 4; u++) {
            float4 mv[8];
            #pragma unroll
            for (int r = 0; r < 8; r++)
                mv[r] = *(const float4*)&Mb[(ty + 8 * r) * MBP + mcol + u * 4];
            #pragma unroll
            for (int jj = 0; jj < 4; jj++) {
                ulonglong2 du = *(const ulonglong2*)(dbase + (u * 4 + jj) * B);
                #pragma unroll
                for (int r = 0; r < 8; r++) {
                    float c = (jj == 0) ? mv[r].x : (jj == 1) ? mv[r].y
                            : (jj == 2) ? mv[r].z : mv[r].w;
                    unsigned long long m = pack2(c);
                    acc[r][0] = fma2(m, du.x, acc[r][0]);
                    acc[r][1] = fma2(m, du.y, acc[r][1]);
                }
            }
        }

        // ---- fold with weight (partial over this chunk's columns) ----
        {
            const float w = CW2[k];
            #pragma unroll
            for (int r = 0; r < 8; r++) {
                int i = 64 * CI2[k] + ty + 8 * r;
                float4 dv = *(const float4*)&Ds[i * B + b0];
                float2 s0 = unpack2(acc[r][0]);
                float2 s1 = unpack2(acc[r][1]);
                q0 += w * dv.x * s0.x;
                q1 += w * dv.y * s0.y;
                q2 += w * dv.z * s1.x;
                q3 += w * dv.w * s1.y;
            }
        }
    }

    // ---- block reduction over 16 groups per b ----
    __syncthreads();
    float* red = Mb;                    // 16*33 floats scratch
    red[g * 33 + b0 + 0] = q0;
    red[g * 33 + b0 + 1] = q1;
    red[g * 33 + b0 + 2] = q2;
    red[g * 33 + b0 + 3] = q3;
    __syncthreads();
    if (tid < B) {
        float acc = 0.f;
        #pragma unroll
        for (int t = 0; t < 16; t++) acc += red[t * 33 + tid];
        g_dist[(size_t)tid * HW + p] = sqrtf(fmaxf(acc, 0.f));
    }
}

// ---------------------------------------------------------------------------
// Kernel 3: build combined operator K = G(blur, reflect-pad) * U(bilinear
// upsample, half-pixel, edge-clamp). K[y][s], y in [0,224), s in [0,56).
// ---------------------------------------------------------------------------
__global__ void kinit_kernel()
{
    __shared__ float g[KS];
    const int y = threadIdx.x;
    if (y < KS) {
        float x = (float)(y - 16);
        g[y] = expf(-(x * x) / 32.f);
    }
    __syncthreads();
    float gs = 0.f;
    #pragma unroll
    for (int i = 0; i < KS; i++) gs += g[i];
    const float inv = 1.f / gs;

    float acc[56];
    #pragma unroll
    for (int s = 0; s < 56; s++) acc[s] = 0.f;

    for (int k = 0; k < KS; k++) {
        int t = y + k - 16;
        if (t < 0) t = -t;
        if (t > OH - 1) t = 2 * (OH - 1) - t;
        float src = 0.25f * t - 0.375f;
        float fs = floorf(src);
        int s0 = (int)fs;
        float a = src - fs;
        int sa = min(max(s0, 0), 55);
        int sb = min(max(s0 + 1, 0), 55);
        float w = g[k] * inv;
        acc[sa] += w * (1.f - a);
        acc[sb] += w * a;
    }
    for (int s = 0; s < 56; s++) {
        g_K[y * 56 + s] = acc[s];
        g_KT[s * OH + y] = acc[s];
    }
}

// ---------------------------------------------------------------------------
// Kernel 4: pass1 (horizontal): tmp[b][y56][x] = sum_s K[x][s] * dist[b][y][s]
// grid = B*14 (4 y-rows per block), block 224.
// ---------------------------------------------------------------------------
__global__ void __launch_bounds__(224)
pass1_kernel()
{
    __shared__ float drow[4][56];
    const int b   = blockIdx.x / 14;
    const int yc0 = (blockIdx.x % 14) * 4;
    const int x   = threadIdx.x;

    for (int i = threadIdx.x; i < 4 * 56; i += 224)
        drow[i / 56][i % 56] = g_dist[(size_t)b * HW + (yc0 + i / 56) * 56 + (i % 56)];
    __syncthreads();

    float acc[4];
    #pragma unroll
    for (int r = 0; r < 4; r++) acc[r] = 0.f;

    #pragma unroll 8
    for (int s = 0; s < 56; s++) {
        float w = g_KT[s * OH + x];
        #pragma unroll
        for (int r = 0; r < 4; r++) acc[r] += w * drow[r][s];
    }
    #pragma unroll
    for (int r = 0; r < 4; r++)
        g_tmp[((size_t)b * 56 + yc0 + r) * OW + x] = acc[r];
}

// ---------------------------------------------------------------------------
// Kernel 5: pass2 (vertical): out[b][y][x] = sum_s K[y][s] * tmp[b][s][x]
// grid = B*8 (28 y-rows per block), block 224. tmp slab (56x224) in smem.
// ---------------------------------------------------------------------------
__global__ void __launch_bounds__(224)
pass2_kernel(float* __restrict__ out)
{
    extern __shared__ float p2[];
    float* slab = p2;              // 56*224 = 12544 floats
    float* Ks   = p2 + 56 * OW;    // 28*56  = 1568 floats

    const int b  = blockIdx.x >> 3;
    const int y0 = (blockIdx.x & 7) * 28;
    const int x  = threadIdx.x;

    const float* tsrc = g_tmp + (size_t)b * 56 * OW;
    for (int i = threadIdx.x; i < 56 * OW; i += 224) slab[i] = tsrc[i];
    for (int i = threadIdx.x; i < 28 * 56; i += 224)
        Ks[i] = g_K[(y0 + i / 56) * 56 + (i % 56)];
    __syncthreads();

    #pragma unroll 4
    for (int yy = 0; yy < 28; yy++) {
        float acc = 0.f;
        #pragma unroll 8
        for (int s = 0; s < 56; s++)
            acc += Ks[yy * 56 + s] * slab[s * OW + x];
        out[((size_t)b * OH + y0 + yy) * OW + x] = acc;
    }
}

// ---------------------------------------------------------------------------
// Launch
// ---------------------------------------------------------------------------
extern "C" void kernel_launch(void* const* d_in, const int* in_sizes, int n_in,
                              void* d_out, int out_size)
{
    const float* emb    = (const float*)d_in[0];
    const float* mean   = (const float*)d_in[1];
    const float* invcov = (const float*)d_in[2];
    float* out = (float*)d_out;

    const int mahal_smem = (C * B + 64 * MBP) * (int)sizeof(float);   // 34816
    cudaFuncSetAttribute(mahal_kernel,
                         cudaFuncAttributeMaxDynamicSharedMemorySize, mahal_smem);
    const int p2_smem = (56 * OW + 28 * 56) * (int)sizeof(float);     // 56448
    cudaFuncSetAttribute(pass2_kernel,
                         cudaFuncAttributeMaxDynamicSharedMemorySize, p2_smem);

    kinit_kernel<<<1, 224>>>();

    dim3 prep_grid(HW / 32, C / 8);
    prep_delta_kernel<<<prep_grid, 256>>>(emb, mean);

    mahal_kernel<<<HW, 128, mahal_smem>>>(invcov);

    pass1_kernel<<<B * 14, 224>>>();
    pass2_kernel<<<B * 8, 224, p2_smem>>>(out);
}

// round 13
// speedup vs baseline: 1.1149x; 1.0737x over previous
#include <cuda_runtime.h>
#include <math.h>

// Problem constants
#define B  32
#define C  200
#define H  56
#define W  56
#define HW 3136
#define OH 224
#define OW 224
#define KS 33
#define NT 12           // compacted taps per output row

#define MSP2 68         // 64x64 chunk pitch (floats)

// Scratch (device globals) — g_delta layout: [hw][c][b]
__device__ float g_delta[(size_t)HW * C * B];
__device__ float g_dist[(size_t)B * HW];          // [b][hw]
__device__ float g_tmp[(size_t)B * 56 * OW];      // [b][y56][x224]
__device__ float g_K12[OH * NT];                  // compacted operator [y][t]
__device__ float g_KT12[NT * OH];                 // transposed [t][y]
__device__ int   g_s0[OH];                        // window start per y

// ---------------- packed f32x2 helpers ----------------
__device__ __forceinline__ unsigned long long fma2(unsigned long long a,
                                                   unsigned long long b,
                                                   unsigned long long c)
{
    unsigned long long d;
    asm("fma.rn.f32x2 %0, %1, %2, %3;" : "=l"(d) : "l"(a), "l"(b), "l"(c));
    return d;
}
__device__ __forceinline__ unsigned long long pack2(float x)
{
    unsigned long long d;
    asm("mov.b64 %0, {%1, %1};" : "=l"(d) : "f"(x));
    return d;
}
__device__ __forceinline__ float2 unpack2(unsigned long long v)
{
    float2 r;
    asm("mov.b64 {%0, %1}, %2;" : "=f"(r.x), "=f"(r.y) : "l"(v));
    return r;
}

// ---------------------------------------------------------------------------
// Kernel 1: delta transpose prepass: emb[b][c][hw] -> g_delta[hw][c][b]
// ---------------------------------------------------------------------------
__global__ void prep_delta_kernel(const float* __restrict__ emb,
                                  const float* __restrict__ mean)
{
    __shared__ float s[8][32][33];
    const int hw0 = blockIdx.x * 32;
    const int c0  = blockIdx.y * 8;
    const int lane = threadIdx.x & 31;
    const int wrp  = threadIdx.x >> 5;

    const int c = c0 + wrp;
    const float m = mean[(size_t)c * HW + hw0 + lane];
    #pragma unroll 4
    for (int b = 0; b < B; b++) {
        float e = emb[((size_t)b * C + c) * HW + hw0 + lane];
        s[wrp][b][lane] = e - m;
    }
    __syncthreads();

    const int b  = threadIdx.x & 31;
    const int cl = threadIdx.x >> 5;
    #pragma unroll 4
    for (int hwl = 0; hwl < 32; hwl++) {
        g_delta[(size_t)(hw0 + hwl) * (C * B) + (c0 + cl) * B + b] = s[cl][b][hwl];
    }
}

// ---------------------------------------------------------------------------
// Kernel 2: per-pixel mahalanobis — EXACT R8 instruction stream with a
// single M smem buffer (double buffer removed; R8 synced every chunk anyway).
// smem = 25.6KB (Ds) + 17.4KB (Mb) = 43.0KB -> 4 CTAs/SM.
// 128 thr = 2 jg x 8 ty x 8 tx; 8 rows x 4 batches per thread, 32-col range.
// ---------------------------------------------------------------------------
__global__ void __launch_bounds__(128, 4)
mahal_kernel(const float* __restrict__ invcov)
{
    extern __shared__ float sm[];
    float* Ds = sm;                       // 6400 floats [j][b]
    float* Mb = sm + C * B;               // 64*68 floats (also border staging)

    const int p   = blockIdx.x;
    const int tid = threadIdx.x;
    const int tx  = tid & 7;
    const int g   = tid >> 3;
    const int ty  = g & 7;
    const int jg  = g >> 3;
    const int b0  = tx * 4;

    const float* Mp = invcov + (size_t)p * (C * C);

    const int   CI[6] = {0, 1, 1, 2, 2, 2};
    const int   CJ[6] = {0, 0, 1, 0, 1, 2};
    const float CW[6] = {1.f, 2.f, 1.f, 2.f, 2.f, 1.f};

    float4 st[8];
    #pragma unroll
    for (int o = 0; o < 8; o++) {
        int e4 = o * 128 + tid;
        int il = e4 >> 4;
        int jl = (e4 & 15) * 4;
        st[o] = *(const float4*)&Mp[(size_t)il * C + jl];
    }

    const float* dsrc = g_delta + (size_t)p * (C * B);
    #pragma unroll
    for (int i = tid * 4; i < C * B; i += 512)
        *(float4*)&Ds[i] = *(const float4*)&dsrc[i];

    #pragma unroll
    for (int i = tid * 4; i < 8 * C; i += 512)
        *(float4*)&Mb[i] = *(const float4*)&Mp[(size_t)192 * C + i];

    __syncthreads();

    float q0 = 0.f, q1 = 0.f, q2 = 0.f, q3 = 0.f;

    // border strip rows 192..199
    #pragma unroll
    for (int rr = 0; rr < 8; rr++) {
        const float* mrow = &Mb[rr * C];
        float p0 = 0.f, p1 = 0.f, p2 = 0.f, p3 = 0.f;
        #pragma unroll
        for (int s = 0; s < 12; s++) {
            int j = g + 16 * s;
            float wm = 2.f * mrow[j];
            float4 dj = *(const float4*)&Ds[j * B + b0];
            p0 += wm * dj.x; p1 += wm * dj.y;
            p2 += wm * dj.z; p3 += wm * dj.w;
        }
        if (g < 8) {
            int j = 192 + g;
            float wm = mrow[j];
            float4 dj = *(const float4*)&Ds[j * B + b0];
            p0 += wm * dj.x; p1 += wm * dj.y;
            p2 += wm * dj.z; p3 += wm * dj.w;
        }
        float4 di = *(const float4*)&Ds[(192 + rr) * B + b0];
        q0 += di.x * p0; q1 += di.y * p1; q2 += di.z * p2; q3 += di.w * p3;
    }

    // 6-chunk pipeline over 64x64 blocks, single smem buffer
    #pragma unroll
    for (int k = 0; k < 6; k++) {
        __syncthreads();                       // prior readers of Mb done
        #pragma unroll
        for (int o = 0; o < 8; o++) {
            int e4 = o * 128 + tid;
            int il = e4 >> 4;
            int jl = (e4 & 15) * 4;
            *(float4*)&Mb[il * MSP2 + jl] = st[o];
        }
        __syncthreads();

        if (k < 5) {
            const float* src = Mp + (size_t)(64 * CI[k + 1]) * C + 64 * CJ[k + 1];
            #pragma unroll
            for (int o = 0; o < 8; o++) {
                int e4 = o * 128 + tid;
                int il = e4 >> 4;
                int jl = (e4 & 15) * 4;
                st[o] = *(const float4*)&src[(size_t)il * C + jl];
            }
        }

        unsigned long long acc[8][2];
        #pragma unroll
        for (int r = 0; r < 8; r++) { acc[r][0] = 0ull; acc[r][1] = 0ull; }

        const float* dbase = &Ds[(64 * CJ[k] + jg * 32) * B + b0];
        const int mcol = jg * 32;
        #pragma unroll
        for (int u = 0; u < 8; u++) {
            float4 mv[8];
            #pragma unroll
            for (int r = 0; r < 8; r++)
                mv[r] = *(const float4*)&Mb[(ty + 8 * r) * MSP2 + mcol + u * 4];
            #pragma unroll
            for (int jj = 0; jj < 4; jj++) {
                ulonglong2 du = *(const ulonglong2*)(dbase + (u * 4 + jj) * B);
                #pragma unroll
                for (int r = 0; r < 8; r++) {
                    float c = (jj == 0) ? mv[r].x : (jj == 1) ? mv[r].y
                            : (jj == 2) ? mv[r].z : mv[r].w;
                    unsigned long long m = pack2(c);
                    acc[r][0] = fma2(m, du.x, acc[r][0]);
                    acc[r][1] = fma2(m, du.y, acc[r][1]);
                }
            }
        }

        {
            const float w = CW[k];
            #pragma unroll
            for (int r = 0; r < 8; r++) {
                int i = 64 * CI[k] + ty + 8 * r;
                float4 dv = *(const float4*)&Ds[i * B + b0];
                float2 s0 = unpack2(acc[r][0]);
                float2 s1 = unpack2(acc[r][1]);
                q0 += w * dv.x * s0.x;
                q1 += w * dv.y * s0.y;
                q2 += w * dv.z * s1.x;
                q3 += w * dv.w * s1.y;
            }
        }
    }

    __syncthreads();
    float* red = Mb;
    red[g * 33 + b0 + 0] = q0;
    red[g * 33 + b0 + 1] = q1;
    red[g * 33 + b0 + 2] = q2;
    red[g * 33 + b0 + 3] = q3;
    __syncthreads();
    if (tid < B) {
        float acc = 0.f;
        #pragma unroll
        for (int t = 0; t < 16; t++) acc += red[t * 33 + tid];
        g_dist[(size_t)tid * HW + p] = sqrtf(fmaxf(acc, 0.f));
    }
}

// ---------------------------------------------------------------------------
// Kernel 3: build COMPACTED operator. Full row K[y][0..55] has support of
// width <=10; store 12 taps starting at s0(y) = clamp(floor(0.25y-4.375),0,44).
// ---------------------------------------------------------------------------
__global__ void kinit_kernel()
{
    __shared__ float g[KS];
    const int y = threadIdx.x;
    if (y < KS) {
        float x = (float)(y - 16);
        g[y] = expf(-(x * x) / 32.f);
    }
    __syncthreads();
    float gs = 0.f;
    #pragma unroll
    for (int i = 0; i < KS; i++) gs += g[i];
    const float inv = 1.f / gs;

    float acc[56];
    #pragma unroll
    for (int s = 0; s < 56; s++) acc[s] = 0.f;

    for (int k = 0; k < KS; k++) {
        int t = y + k - 16;
        if (t < 0) t = -t;
        if (t > OH - 1) t = 2 * (OH - 1) - t;
        float src = 0.25f * t - 0.375f;
        float fs = floorf(src);
        int s0 = (int)fs;
        float a = src - fs;
        int sa = min(max(s0, 0), 55);
        int sb = min(max(s0 + 1, 0), 55);
        float w = g[k] * inv;
        acc[sa] += w * (1.f - a);
        acc[sb] += w * a;
    }

    int s0 = (int)floorf(0.25f * y - 4.375f);
    s0 = min(max(s0, 0), 56 - NT);
    g_s0[y] = s0;
    for (int t = 0; t < NT; t++) {
        float v = acc[s0 + t];
        g_K12[y * NT + t] = v;
        g_KT12[t * OH + y] = v;
    }
}

// ---------------------------------------------------------------------------
// Kernel 4: pass1 (horizontal, 12 taps):
// tmp[b][y56][x] = sum_t K12[x][t] * dist[b][y][s0[x]+t]
// grid = B*14 (4 y-rows per block), block 224.
// ---------------------------------------------------------------------------
__global__ void __launch_bounds__(224)
pass1_kernel()
{
    __shared__ float drow[4][56];
    const int b   = blockIdx.x / 14;
    const int yc0 = (blockIdx.x % 14) * 4;
    const int x   = threadIdx.x;

    for (int i = threadIdx.x; i < 4 * 56; i += 224)
        drow[i / 56][i % 56] = g_dist[(size_t)b * HW + (yc0 + i / 56) * 56 + (i % 56)];

    const int s0 = g_s0[x];
    float kw[NT];
    #pragma unroll
    for (int t = 0; t < NT; t++) kw[t] = g_KT12[t * OH + x];
    __syncthreads();

    float acc[4] = {0.f, 0.f, 0.f, 0.f};
    #pragma unroll
    for (int t = 0; t < NT; t++) {
        #pragma unroll
        for (int r = 0; r < 4; r++) acc[r] += kw[t] * drow[r][s0 + t];
    }
    #pragma unroll
    for (int r = 0; r < 4; r++)
        g_tmp[((size_t)b * 56 + yc0 + r) * OW + x] = acc[r];
}

// ---------------------------------------------------------------------------
// Kernel 5: pass2 (vertical, 12 taps):
// out[b][y][x] = sum_t K12[y][t] * tmp[b][s0[y]+t][x]
// grid = B*8 (28 y-rows per block), block 224. tmp slab in smem.
// ---------------------------------------------------------------------------
__global__ void __launch_bounds__(224)
pass2_kernel(float* __restrict__ out)
{
    extern __shared__ float p2[];
    float* slab = p2;                  // 56*224 floats
    float* Ks   = p2 + 56 * OW;        // 28*NT floats
    int*   S0s  = (int*)(Ks + 28 * NT);// 28 ints

    const int b  = blockIdx.x >> 3;
    const int y0 = (blockIdx.x & 7) * 28;
    const int x  = threadIdx.x;

    const float* tsrc = g_tmp + (size_t)b * 56 * OW;
    for (int i = threadIdx.x; i < 56 * OW; i += 224) slab[i] = tsrc[i];
    for (int i = threadIdx.x; i < 28 * NT; i += 224)
        Ks[i] = g_K12[(y0 + i / NT) * NT + (i % NT)];
    if (threadIdx.x < 28) S0s[threadIdx.x] = g_s0[y0 + threadIdx.x];
    __syncthreads();

    #pragma unroll 4
    for (int yy = 0; yy < 28; yy++) {
        const int s0 = S0s[yy];
        float acc = 0.f;
        #pragma unroll
        for (int t = 0; t < NT; t++)
            acc += Ks[yy * NT + t] * slab[(s0 + t) * OW + x];
        out[((size_t)b * OH + y0 + yy) * OW + x] = acc;
    }
}

// ---------------------------------------------------------------------------
// Launch
// ---------------------------------------------------------------------------
extern "C" void kernel_launch(void* const* d_in, const int* in_sizes, int n_in,
                              void* d_out, int out_size)
{
    const float* emb    = (const float*)d_in[0];
    const float* mean   = (const float*)d_in[1];
    const float* invcov = (const float*)d_in[2];
    float* out = (float*)d_out;

    const int mahal_smem = (C * B + 64 * MSP2) * (int)sizeof(float);  // 43008
    cudaFuncSetAttribute(mahal_kernel,
                         cudaFuncAttributeMaxDynamicSharedMemorySize, mahal_smem);
    const int p2_smem = (56 * OW + 28 * NT) * (int)sizeof(float) + 28 * (int)sizeof(int);
    cudaFuncSetAttribute(pass2_kernel,
                         cudaFuncAttributeMaxDynamicSharedMemorySize, p2_smem);

    kinit_kernel<<<1, 224>>>();

    dim3 prep_grid(HW / 32, C / 8);
    prep_delta_kernel<<<prep_grid, 256>>>(emb, mean);

    mahal_kernel<<<HW, 128, mahal_smem>>>(invcov);

    pass1_kernel<<<B * 14, 224>>>();
    pass2_kernel<<<B * 8, 224, p2_smem>>>(out);
}

// round 14
// speedup vs baseline: 1.2845x; 1.1522x over previous
#include <cuda_runtime.h>
#include <math.h>

// Problem constants
#define B  32
#define C  200
#define H  56
#define W  56
#define HW 3136
#define OH 224
#define OW 224
#define KS 33
#define NT 12           // compacted taps per output row

#define MSP2 68         // 64x64 chunk pitch (floats)

// Scratch (device globals) — g_delta layout: [hw][c][b]
__device__ float g_delta[(size_t)HW * C * B];
__device__ float g_dist[(size_t)B * HW];          // [b][hw]
__device__ float g_tmp[(size_t)B * 56 * OW];      // [b][y56][x224]
__device__ float g_K12[OH * NT];                  // compacted operator [y][t]
__device__ float g_KT12[NT * OH];                 // transposed [t][y]
__device__ int   g_s0[OH];                        // window start per y

// ---------------- packed f32x2 / async helpers ----------------
__device__ __forceinline__ unsigned long long fma2(unsigned long long a,
                                                   unsigned long long b,
                                                   unsigned long long c)
{
    unsigned long long d;
    asm("fma.rn.f32x2 %0, %1, %2, %3;" : "=l"(d) : "l"(a), "l"(b), "l"(c));
    return d;
}
__device__ __forceinline__ unsigned long long pack2(float x)
{
    unsigned long long d;
    asm("mov.b64 %0, {%1, %1};" : "=l"(d) : "f"(x));
    return d;
}
__device__ __forceinline__ float2 unpack2(unsigned long long v)
{
    float2 r;
    asm("mov.b64 {%0, %1}, %2;" : "=f"(r.x), "=f"(r.y) : "l"(v));
    return r;
}
__device__ __forceinline__ void cp16(const void* smem_dst, const void* gmem_src)
{
    unsigned int s = (unsigned int)__cvta_generic_to_shared(smem_dst);
    asm volatile("cp.async.cg.shared.global [%0], [%1], 16;" :: "r"(s), "l"(gmem_src));
}
#define CP_COMMIT() asm volatile("cp.async.commit_group;")
#define CP_WAIT0()  asm volatile("cp.async.wait_group 0;")

// ---------------------------------------------------------------------------
// Kernel 1: delta transpose prepass: emb[b][c][hw] -> g_delta[hw][c][b]
// ---------------------------------------------------------------------------
__global__ void prep_delta_kernel(const float* __restrict__ emb,
                                  const float* __restrict__ mean)
{
    __shared__ float s[8][32][33];
    const int hw0 = blockIdx.x * 32;
    const int c0  = blockIdx.y * 8;
    const int lane = threadIdx.x & 31;
    const int wrp  = threadIdx.x >> 5;

    const int c = c0 + wrp;
    const float m = mean[(size_t)c * HW + hw0 + lane];
    #pragma unroll 4
    for (int b = 0; b < B; b++) {
        float e = emb[((size_t)b * C + c) * HW + hw0 + lane];
        s[wrp][b][lane] = e - m;
    }
    __syncthreads();

    const int b  = threadIdx.x & 31;
    const int cl = threadIdx.x >> 5;
    #pragma unroll 4
    for (int hwl = 0; hwl < 32; hwl++) {
        g_delta[(size_t)(hw0 + hwl) * (C * B) + (c0 + cl) * B + b] = s[cl][b][hwl];
    }
}

// ---------------------------------------------------------------------------
// Kernel 2: per-pixel mahalanobis — R13 structure with cp.async M staging
// (no register staging -> ~85 regs) and 5 CTAs/SM.
// smem = 25.6KB (Ds) + 17.4KB (Mb) = 43.0KB.
// 128 thr = 2 jg x 8 ty x 8 tx; 8 rows x 4 batches per thread, 32-col range.
// ---------------------------------------------------------------------------
__global__ void __launch_bounds__(128, 5)
mahal_kernel(const float* __restrict__ invcov)
{
    extern __shared__ float sm[];
    float* Ds = sm;                       // 6400 floats [j][b]
    float* Mb = sm + C * B;               // 64*68 floats (also border staging)

    const int p   = blockIdx.x;
    const int tid = threadIdx.x;
    const int tx  = tid & 7;
    const int g   = tid >> 3;
    const int ty  = g & 7;
    const int jg  = g >> 3;
    const int b0  = tx * 4;

    const float* Mp = invcov + (size_t)p * (C * C);

    const int   CI[6] = {0, 1, 1, 2, 2, 2};
    const int   CJ[6] = {0, 0, 1, 0, 1, 2};
    const float CW[6] = {1.f, 2.f, 1.f, 2.f, 2.f, 1.f};

    // ---- stage delta (coalesced) + border rows via cp.async ----
    const float* dsrc = g_delta + (size_t)p * (C * B);
    #pragma unroll
    for (int i = tid * 4; i < C * B; i += 512)
        cp16(&Ds[i], &dsrc[i]);
    #pragma unroll
    for (int i = tid * 4; i < 8 * C; i += 512)
        cp16(&Mb[i], &Mp[(size_t)192 * C + i]);
    CP_COMMIT();
    CP_WAIT0();
    __syncthreads();

    float q0 = 0.f, q1 = 0.f, q2 = 0.f, q3 = 0.f;

    // ---- border strip rows 192..199 (reads Mb staging) ----
    #pragma unroll
    for (int rr = 0; rr < 8; rr++) {
        const float* mrow = &Mb[rr * C];
        float p0 = 0.f, p1 = 0.f, p2 = 0.f, p3 = 0.f;
        #pragma unroll
        for (int s = 0; s < 12; s++) {
            int j = g + 16 * s;
            float wm = 2.f * mrow[j];
            float4 dj = *(const float4*)&Ds[j * B + b0];
            p0 += wm * dj.x; p1 += wm * dj.y;
            p2 += wm * dj.z; p3 += wm * dj.w;
        }
        if (g < 8) {
            int j = 192 + g;
            float wm = mrow[j];
            float4 dj = *(const float4*)&Ds[j * B + b0];
            p0 += wm * dj.x; p1 += wm * dj.y;
            p2 += wm * dj.z; p3 += wm * dj.w;
        }
        float4 di = *(const float4*)&Ds[(192 + rr) * B + b0];
        q0 += di.x * p0; q1 += di.y * p1; q2 += di.z * p2; q3 += di.w * p3;
    }

    // ---- 6-chunk pipeline, cp.async into single Mb buffer ----
    #pragma unroll
    for (int k = 0; k < 6; k++) {
        __syncthreads();                       // prior readers of Mb done
        {
            const float* src = Mp + (size_t)(64 * CI[k]) * C + 64 * CJ[k];
            #pragma unroll
            for (int o = 0; o < 8; o++) {
                int e4 = o * 128 + tid;
                int il = e4 >> 4;
                int jl = (e4 & 15) * 4;
                cp16(&Mb[il * MSP2 + jl], &src[(size_t)il * C + jl]);
            }
            CP_COMMIT();
            CP_WAIT0();
        }
        __syncthreads();

        unsigned long long acc[8][2];
        #pragma unroll
        for (int r = 0; r < 8; r++) { acc[r][0] = 0ull; acc[r][1] = 0ull; }

        const float* dbase = &Ds[(64 * CJ[k] + jg * 32) * B + b0];
        const int mcol = jg * 32;
        #pragma unroll
        for (int u = 0; u < 8; u++) {
            float4 mv[8];
            #pragma unroll
            for (int r = 0; r < 8; r++)
                mv[r] = *(const float4*)&Mb[(ty + 8 * r) * MSP2 + mcol + u * 4];
            #pragma unroll
            for (int jj = 0; jj < 4; jj++) {
                ulonglong2 du = *(const ulonglong2*)(dbase + (u * 4 + jj) * B);
                #pragma unroll
                for (int r = 0; r < 8; r++) {
                    float c = (jj == 0) ? mv[r].x : (jj == 1) ? mv[r].y
                            : (jj == 2) ? mv[r].z : mv[r].w;
                    unsigned long long m = pack2(c);
                    acc[r][0] = fma2(m, du.x, acc[r][0]);
                    acc[r][1] = fma2(m, du.y, acc[r][1]);
                }
            }
        }

        {
            const float w = CW[k];
            #pragma unroll
            for (int r = 0; r < 8; r++) {
                int i = 64 * CI[k] + ty + 8 * r;
                float4 dv = *(const float4*)&Ds[i * B + b0];
                float2 s0 = unpack2(acc[r][0]);
                float2 s1 = unpack2(acc[r][1]);
                q0 += w * dv.x * s0.x;
                q1 += w * dv.y * s0.y;
                q2 += w * dv.z * s1.x;
                q3 += w * dv.w * s1.y;
            }
        }
    }

    __syncthreads();
    float* red = Mb;
    red[g * 33 + b0 + 0] = q0;
    red[g * 33 + b0 + 1] = q1;
    red[g * 33 + b0 + 2] = q2;
    red[g * 33 + b0 + 3] = q3;
    __syncthreads();
    if (tid < B) {
        float acc = 0.f;
        #pragma unroll
        for (int t = 0; t < 16; t++) acc += red[t * 33 + tid];
        g_dist[(size_t)tid * HW + p] = sqrtf(fmaxf(acc, 0.f));
    }
}

// ---------------------------------------------------------------------------
// Kernel 3: build COMPACTED operator (12 taps per row, window start s0).
// ---------------------------------------------------------------------------
__global__ void kinit_kernel()
{
    __shared__ float g[KS];
    const int y = threadIdx.x;
    if (y < KS) {
        float x = (float)(y - 16);
        g[y] = expf(-(x * x) / 32.f);
    }
    __syncthreads();
    float gs = 0.f;
    #pragma unroll
    for (int i = 0; i < KS; i++) gs += g[i];
    const float inv = 1.f / gs;

    float acc[56];
    #pragma unroll
    for (int s = 0; s < 56; s++) acc[s] = 0.f;

    for (int k = 0; k < KS; k++) {
        int t = y + k - 16;
        if (t < 0) t = -t;
        if (t > OH - 1) t = 2 * (OH - 1) - t;
        float src = 0.25f * t - 0.375f;
        float fs = floorf(src);
        int s0 = (int)fs;
        float a = src - fs;
        int sa = min(max(s0, 0), 55);
        int sb = min(max(s0 + 1, 0), 55);
        float w = g[k] * inv;
        acc[sa] += w * (1.f - a);
        acc[sb] += w * a;
    }

    int s0 = (int)floorf(0.25f * y - 4.375f);
    s0 = min(max(s0, 0), 56 - NT);
    g_s0[y] = s0;
    for (int t = 0; t < NT; t++) {
        float v = acc[s0 + t];
        g_K12[y * NT + t] = v;
        g_KT12[t * OH + y] = v;
    }
}

// ---------------------------------------------------------------------------
// Kernel 4: pass1 (horizontal, 12 taps)
// ---------------------------------------------------------------------------
__global__ void __launch_bounds__(224)
pass1_kernel()
{
    __shared__ float drow[4][56];
    const int b   = blockIdx.x / 14;
    const int yc0 = (blockIdx.x % 14) * 4;
    const int x   = threadIdx.x;

    for (int i = threadIdx.x; i < 4 * 56; i += 224)
        drow[i / 56][i % 56] = g_dist[(size_t)b * HW + (yc0 + i / 56) * 56 + (i % 56)];

    const int s0 = g_s0[x];
    float kw[NT];
    #pragma unroll
    for (int t = 0; t < NT; t++) kw[t] = g_KT12[t * OH + x];
    __syncthreads();

    float acc[4] = {0.f, 0.f, 0.f, 0.f};
    #pragma unroll
    for (int t = 0; t < NT; t++) {
        #pragma unroll
        for (int r = 0; r < 4; r++) acc[r] += kw[t] * drow[r][s0 + t];
    }
    #pragma unroll
    for (int r = 0; r < 4; r++)
        g_tmp[((size_t)b * 56 + yc0 + r) * OW + x] = acc[r];
}

// ---------------------------------------------------------------------------
// Kernel 5: pass2 (vertical, 12 taps)
// ---------------------------------------------------------------------------
__global__ void __launch_bounds__(224)
pass2_kernel(float* __restrict__ out)
{
    extern __shared__ float p2[];
    float* slab = p2;                  // 56*224 floats
    float* Ks   = p2 + 56 * OW;        // 28*NT floats
    int*   S0s  = (int*)(Ks + 28 * NT);// 28 ints

    const int b  = blockIdx.x >> 3;
    const int y0 = (blockIdx.x & 7) * 28;
    const int x  = threadIdx.x;

    const float* tsrc = g_tmp + (size_t)b * 56 * OW;
    for (int i = threadIdx.x; i < 56 * OW; i += 224) slab[i] = tsrc[i];
    for (int i = threadIdx.x; i < 28 * NT; i += 224)
        Ks[i] = g_K12[(y0 + i / NT) * NT + (i % NT)];
    if (threadIdx.x < 28) S0s[threadIdx.x] = g_s0[y0 + threadIdx.x];
    __syncthreads();

    #pragma unroll 4
    for (int yy = 0; yy < 28; yy++) {
        const int s0 = S0s[yy];
        float acc = 0.f;
        #pragma unroll
        for (int t = 0; t < NT; t++)
            acc += Ks[yy * NT + t] * slab[(s0 + t) * OW + x];
        out[((size_t)b * OH + y0 + yy) * OW + x] = acc;
    }
}

// ---------------------------------------------------------------------------
// Launch
// ---------------------------------------------------------------------------
extern "C" void kernel_launch(void* const* d_in, const int* in_sizes, int n_in,
                              void* d_out, int out_size)
{
    const float* emb    = (const float*)d_in[0];
    const float* mean   = (const float*)d_in[1];
    const float* invcov = (const float*)d_in[2];
    float* out = (float*)d_out;

    const int mahal_smem = (C * B + 64 * MSP2) * (int)sizeof(float);  // 43008
    cudaFuncSetAttribute(mahal_kernel,
                         cudaFuncAttributeMaxDynamicSharedMemorySize, mahal_smem);
    const int p2_smem = (56 * OW + 28 * NT) * (int)sizeof(float) + 28 * (int)sizeof(int);
    cudaFuncSetAttribute(pass2_kernel,
                         cudaFuncAttributeMaxDynamicSharedMemorySize, p2_smem);

    kinit_kernel<<<1, 224>>>();

    dim3 prep_grid(HW / 32, C / 8);
    prep_delta_kernel<<<prep_grid, 256>>>(emb, mean);

    mahal_kernel<<<HW, 128, mahal_smem>>>(invcov);

    pass1_kernel<<<B * 14, 224>>>();
    pass2_kernel<<<B * 8, 224, p2_smem>>>(out);
}